// round 10
// baseline (speedup 1.0000x reference)
#include <cuda_runtime.h>
#include <cuda_bf16.h>

#define NBLK 128
#define NTHR 256
#define BB   128
#define TT   512
#define PREDN 24
#define FF   16
#define LL   8
#define HH   1024
#define FROWS (TT + PREDN - 1)

typedef unsigned int uint;

// ---------------- persistent device scratch ---------------------------------
__device__ uint4 g_A0[2][2][8 * 64 * 32];      // hidden states, MMA A-frag order
__device__ uint4 g_A1[2][2][8 * 64 * 32];
// weights split(hi/lo bf16)+permuted: [mat][bid][hc*384 + nf*64 + pl*32 + ln]
__device__ uint4 g_B[4][NBLK][6144];
__device__ float4 g_part[NBLK * 4 * 32 * 18];  // split-K partial exchange
__device__ float g_p[BB * LL];
__device__ unsigned g_count = 0;
__device__ unsigned g_gen = 0;

// ---------------- grid barrier ----------------------------------------------
__device__ __forceinline__ void gbar() {
    __syncthreads();
    if (threadIdx.x == 0) {
        __threadfence();
        volatile unsigned* vg = &g_gen;
        unsigned g = *vg;
        if (atomicAdd(&g_count, 1u) == NBLK - 1) {
            g_count = 0;
            __threadfence();
            *vg = g + 1;
        } else {
            while (*vg == g) {}
        }
        __threadfence();
    }
    __syncthreads();
}

#define CLUSTER_SYNC() do { \
    asm volatile("barrier.cluster.arrive.aligned;" ::: "memory"); \
    asm volatile("barrier.cluster.wait.aligned;" ::: "memory"); \
} while (0)

// ---------------- 2B coherent global ld/st ----------------------------------
__device__ __forceinline__ unsigned short ldcg_u16(const void* p) {
    unsigned short v;
    asm volatile("ld.global.cg.u16 %0, [%1];" : "=h"(v) : "l"(p));
    return v;
}
__device__ __forceinline__ void stcg_u16(void* p, unsigned short v) {
    asm volatile("st.global.cg.u16 [%0], %1;" :: "l"(p), "h"(v));
}

// ---------------- h element <-> fragment-layout mapping ----------------------
__device__ __forceinline__ int h_off(int b, int u) {
    int rg = b >> 4, r = b & 15, kp = u & 15, kg = u >> 4;
    int ireg = (r >> 3) + ((kp >> 3) << 1);
    int ln = (r & 7) * 4 + ((kp & 7) >> 1);
    return ((rg * 64 + kg) * 32 + ln) * 16 + ireg * 4 + (kp & 1) * 2;
}
__device__ __forceinline__ void store_h(uint4* Ph, uint4* Pl, int b, int u, float v) {
    __nv_bfloat16 hi = __float2bfloat16(v);
    __nv_bfloat16 lo = __float2bfloat16(v - __bfloat162float(hi));
    int off = h_off(b, u);
    stcg_u16((char*)Ph + off, __bfloat16_as_ushort(hi));
    stcg_u16((char*)Pl + off, __bfloat16_as_ushort(lo));
}
__device__ __forceinline__ float load_h(const uint4* Ph, const uint4* Pl, int b, int u) {
    int off = h_off(b, u);
    float hi = __bfloat162float(__ushort_as_bfloat16(ldcg_u16((const char*)Ph + off)));
    float lo = __bfloat162float(__ushort_as_bfloat16(ldcg_u16((const char*)Pl + off)));
    return hi + lo;
}

// ---------------- HMMA m16n8k16 bf16 -> f32 ----------------------------------
__device__ __forceinline__ void mma16816(float* c, const uint* a, uint b0, uint b1) {
    asm volatile(
        "mma.sync.aligned.m16n8k16.row.col.f32.bf16.bf16.f32 "
        "{%0,%1,%2,%3}, {%4,%5,%6,%7}, {%8,%9}, {%0,%1,%2,%3};"
        : "+f"(c[0]), "+f"(c[1]), "+f"(c[2]), "+f"(c[3])
        : "r"(a[0]), "r"(a[1]), "r"(a[2]), "r"(a[3]), "r"(b0), "r"(b1));
}

// ---------------- streamed-B ring (2 slots x 384 uint4) -----------------------
__device__ __forceinline__ void issue_ring(const uint4* __restrict__ gsrc,
                                           uint ring_addr, int hc, int t) {
    const uint4* src = gsrc + hc * 384;
    uint dst = ring_addr + (uint)((hc & 1) * 384 * 16);
    asm volatile("cp.async.cg.shared.global [%0], [%1], 16;"
                 :: "r"(dst + t * 16), "l"(src + t) : "memory");
    if (t + 256 < 384)
        asm volatile("cp.async.cg.shared.global [%0], [%1], 16;"
                     :: "r"(dst + (t + 256) * 16), "l"(src + t + 256) : "memory");
    asm volatile("cp.async.commit_group;" ::: "memory");
}

// ---------------- GEMM engines -------------------------------------------------
// Warp w: rows [16w,16w+16), all 48 cols, k-slice [kb*512, kb*512+512).
__device__ void gemm_res(const uint4* __restrict__ Ah, const uint4* __restrict__ Al,
                         const uint4* __restrict__ sres, int w, int kb, int lane,
                         float acc[6][4]) {
    #pragma unroll
    for (int nf = 0; nf < 6; nf++)
        #pragma unroll
        for (int i = 0; i < 4; i++) acc[nf][i] = 0.f;
    const uint4* Abh = Ah + (w * 64 + kb * 32) * 32 + lane;
    const uint4* Abl = Al + (w * 64 + kb * 32) * 32 + lane;
    uint4 fah[4][2], fal[4][2];
    #pragma unroll
    for (int j = 0; j < 4; j++) {
        fah[j][0] = __ldcg(Abh + (2 * j) * 32);     fah[j][1] = __ldcg(Abh + (2 * j + 1) * 32);
        fal[j][0] = __ldcg(Abl + (2 * j) * 32);     fal[j][1] = __ldcg(Abl + (2 * j + 1) * 32);
    }
    #pragma unroll 1
    for (int hc = 0; hc < 16; hc++) {
        int j = hc & 3;
        const uint4* bs = sres + hc * 384 + lane;
        #pragma unroll
        for (int nf = 0; nf < 6; nf++) {
            uint4 BH = bs[(nf * 2) * 32];
            uint4 BL = bs[(nf * 2 + 1) * 32];
            const uint* a0h = (const uint*)&fah[j][0];
            const uint* a0l = (const uint*)&fal[j][0];
            const uint* a1h = (const uint*)&fah[j][1];
            const uint* a1l = (const uint*)&fal[j][1];
            mma16816(acc[nf], a0h, BH.x, BH.y);
            mma16816(acc[nf], a0l, BH.x, BH.y);
            mma16816(acc[nf], a0h, BL.x, BL.y);
            mma16816(acc[nf], a1h, BH.z, BH.w);
            mma16816(acc[nf], a1l, BH.z, BH.w);
            mma16816(acc[nf], a1h, BL.z, BL.w);
        }
        if (hc + 4 < 16) {
            fah[j][0] = __ldcg(Abh + (2 * (hc + 4)) * 32);
            fah[j][1] = __ldcg(Abh + (2 * (hc + 4) + 1) * 32);
            fal[j][0] = __ldcg(Abl + (2 * (hc + 4)) * 32);
            fal[j][1] = __ldcg(Abl + (2 * (hc + 4) + 1) * 32);
        }
    }
}

// dual: set S streamed from ring (gsrc), set R resident (sres). One A read.
__device__ void gemm_dual(const uint4* __restrict__ Ah, const uint4* __restrict__ Al,
                          const uint4* __restrict__ sres, uint4* __restrict__ ring,
                          uint ring_addr, const uint4* __restrict__ gsrc,
                          int w, int kb, int lane, int t,
                          float accS[6][4], float accR[6][4]) {
    #pragma unroll
    for (int nf = 0; nf < 6; nf++)
        #pragma unroll
        for (int i = 0; i < 4; i++) { accS[nf][i] = 0.f; accR[nf][i] = 0.f; }
    const uint4* Abh = Ah + (w * 64 + kb * 32) * 32 + lane;
    const uint4* Abl = Al + (w * 64 + kb * 32) * 32 + lane;

    issue_ring(gsrc, ring_addr, 0, t);

    uint4 fah[4][2], fal[4][2];
    #pragma unroll
    for (int j = 0; j < 4; j++) {
        fah[j][0] = __ldcg(Abh + (2 * j) * 32);     fah[j][1] = __ldcg(Abh + (2 * j + 1) * 32);
        fal[j][0] = __ldcg(Abl + (2 * j) * 32);     fal[j][1] = __ldcg(Abl + (2 * j + 1) * 32);
    }
    #pragma unroll 1
    for (int hc = 0; hc < 16; hc++) {
        asm volatile("cp.async.wait_group 0;" ::: "memory");
        __syncthreads();
        if (hc + 1 < 16) issue_ring(gsrc, ring_addr, hc + 1, t);
        int j = hc & 3;
        const uint4* rs = ring + (hc & 1) * 384 + lane;
        const uint4* bs = sres + hc * 384 + lane;
        #pragma unroll
        for (int nf = 0; nf < 6; nf++) {
            uint4 SH = rs[(nf * 2) * 32];
            uint4 SL = rs[(nf * 2 + 1) * 32];
            uint4 RH = bs[(nf * 2) * 32];
            uint4 RL = bs[(nf * 2 + 1) * 32];
            const uint* a0h = (const uint*)&fah[j][0];
            const uint* a0l = (const uint*)&fal[j][0];
            const uint* a1h = (const uint*)&fah[j][1];
            const uint* a1l = (const uint*)&fal[j][1];
            mma16816(accS[nf], a0h, SH.x, SH.y);
            mma16816(accS[nf], a0l, SH.x, SH.y);
            mma16816(accS[nf], a0h, SL.x, SL.y);
            mma16816(accS[nf], a1h, SH.z, SH.w);
            mma16816(accS[nf], a1l, SH.z, SH.w);
            mma16816(accS[nf], a1h, SL.z, SL.w);
            mma16816(accR[nf], a0h, RH.x, RH.y);
            mma16816(accR[nf], a0l, RH.x, RH.y);
            mma16816(accR[nf], a0h, RL.x, RL.y);
            mma16816(accR[nf], a1h, RH.z, RH.w);
            mma16816(accR[nf], a1l, RH.z, RH.w);
            mma16816(accR[nf], a1h, RL.z, RL.w);
        }
        if (hc + 4 < 16) {
            fah[j][0] = __ldcg(Abh + (2 * (hc + 4)) * 32);
            fah[j][1] = __ldcg(Abh + (2 * (hc + 4) + 1) * 32);
            fal[j][0] = __ldcg(Abl + (2 * (hc + 4)) * 32);
            fal[j][1] = __ldcg(Abl + (2 * (hc + 4) + 1) * 32);
        }
    }
}

// ---------------- partial exchange helpers -------------------------------------
__device__ __forceinline__ void part_write(int bid, int w, int lane,
                                           const float a[6][4], int slot) {
    float4* dst = g_part + ((bid * 4 + (w & 3)) * 32 + lane) * 18 + slot * 6;
    #pragma unroll
    for (int nf = 0; nf < 6; nf++)
        __stcg(dst + nf, make_float4(a[nf][0], a[nf][1], a[nf][2], a[nf][3]));
}
__device__ __forceinline__ void part_add(int bid, int w, int lane,
                                         float a[6][4], int slot) {
    const float4* src = g_part + (((bid ^ 1) * 4 + (w & 3)) * 32 + lane) * 18 + slot * 6;
    #pragma unroll
    for (int nf = 0; nf < 6; nf++) {
        float4 v = __ldcg(src + nf);
        a[nf][0] += v.x; a[nf][1] += v.y; a[nf][2] += v.z; a[nf][3] += v.w;
    }
}

// ---------------- GRU update / xproj (owner warps, 48-col layout) --------------
__device__ __forceinline__ float sigf(float x) { return 1.f / (1.f + __expf(-x)); }

__device__ __forceinline__ void upd48(const float gi[6][4], const float gh[6][4],
                                      const float* __restrict__ bih,
                                      const float* __restrict__ bhh,
                                      int u0g, int w, int lane,
                                      const uint4* Phc, const uint4* Plc,
                                      uint4* Phn, uint4* Pln) {
    int rbase = w * 16 + (lane >> 2);
    int ubase = (lane & 3) * 2;
    #pragma unroll
    for (int i = 0; i < 4; i++) {
        int b = rbase + (i >> 1) * 8;
        #pragma unroll
        for (int uhi = 0; uhi < 2; uhi++) {
            int jc = u0g + uhi * 8 + ubase + (i & 1);
            float r = sigf(gi[uhi][i] + __ldg(bih + jc) + gh[uhi][i] + __ldg(bhh + jc));
            float z = sigf(gi[2 + uhi][i] + __ldg(bih + HH + jc) +
                           gh[2 + uhi][i] + __ldg(bhh + HH + jc));
            float n = tanhf(gi[4 + uhi][i] + __ldg(bih + 2 * HH + jc) +
                            r * (gh[4 + uhi][i] + __ldg(bhh + 2 * HH + jc)));
            float ho = Phc ? load_h(Phc, Plc, b, jc) : 0.f;
            store_h(Phn, Pln, b, jc, (1.f - z) * n + z * ho);
        }
    }
}

__device__ __forceinline__ void xproj48(const float* __restrict__ sh_x,
                                        const float* __restrict__ sh_wi,
                                        int w, int lane, float xp[6][4]) {
    int rbase = w * 16 + (lane >> 2);
    int ubase = (lane & 3) * 2;
    #pragma unroll
    for (int nf = 0; nf < 6; nf++)
        #pragma unroll
        for (int i = 0; i < 4; i++) xp[nf][i] = 0.f;
    #pragma unroll 1
    for (int k = 0; k < 24; k++) {
        float wi[2][2][3];
        #pragma unroll
        for (int uhi = 0; uhi < 2; uhi++)
            #pragma unroll
            for (int q = 0; q < 2; q++) {
                int u = uhi * 8 + ubase + q;
                wi[uhi][q][0] = sh_wi[k * 48 + u];
                wi[uhi][q][1] = sh_wi[k * 48 + 16 + u];
                wi[uhi][q][2] = sh_wi[k * 48 + 32 + u];
            }
        float xv0 = sh_x[rbase * 24 + k];
        float xv1 = sh_x[(rbase + 8) * 24 + k];
        #pragma unroll
        for (int uhi = 0; uhi < 2; uhi++)
            #pragma unroll
            for (int q = 0; q < 2; q++) {
                xp[uhi][q]         += xv0 * wi[uhi][q][0];
                xp[2 + uhi][q]     += xv0 * wi[uhi][q][1];
                xp[4 + uhi][q]     += xv0 * wi[uhi][q][2];
                xp[uhi][2 + q]     += xv1 * wi[uhi][q][0];
                xp[2 + uhi][2 + q] += xv1 * wi[uhi][q][1];
                xp[4 + uhi][2 + q] += xv1 * wi[uhi][q][2];
            }
    }
}

// ---------------- misc ----------------------------------------------------------
__device__ __forceinline__ void load_wi48(const float* __restrict__ Wih, int u0g,
                                          float* __restrict__ sh_wi) {
    for (int idx = threadIdx.x; idx < 24 * 48; idx += NTHR) {
        int k = idx / 48, j = idx % 48;
        int g = j / 16, uu = j % 16;
        sh_wi[k * 48 + j] = Wih[(long)(g * HH + u0g + uu) * 24 + k];
    }
}

__device__ __forceinline__ void fc_phase(const uint4* Ph, const uint4* Pl,
                                         const float* __restrict__ fcW,
                                         const float* __restrict__ fcb,
                                         float* __restrict__ outp) {
    int b = blockIdx.x;
    int w = threadIdx.x >> 5;
    int lane = threadIdx.x & 31;
    float s = 0.f;
    #pragma unroll
    for (int c = 0; c < 32; c++) {
        int u = c * 32 + lane;
        s += load_h(Ph, Pl, b, u) * fcW[(long)w * HH + u];
    }
    #pragma unroll
    for (int o = 16; o; o >>= 1) s += __shfl_down_sync(0xffffffffu, s, o);
    if (lane == 0) {
        float v = s + fcb[w];
        outp[b * LL + w] = v;
        asm volatile("st.global.cg.f32 [%0], %1;" :: "l"(g_p + b * LL + w), "f"(v));
    }
}

// ---------------- persistent kernel -----------------------------------------
__global__ void __launch_bounds__(NTHR, 1) __cluster_dims__(2, 1, 1)
gru_persistent(
    const float* __restrict__ feats, const float* __restrict__ labels,
    const float* __restrict__ y, const int* __restrict__ teacher,
    const float* __restrict__ eWih0, const float* __restrict__ eWhh0,
    const float* __restrict__ ebih0, const float* __restrict__ ebhh0,
    const float* __restrict__ eWih1, const float* __restrict__ eWhh1,
    const float* __restrict__ ebih1, const float* __restrict__ ebhh1,
    const float* __restrict__ dWih, const float* __restrict__ dWhh,
    const float* __restrict__ dbih, const float* __restrict__ dbhh,
    const float* __restrict__ fcW, const float* __restrict__ fcb,
    float* __restrict__ out)
{
    extern __shared__ __align__(16) unsigned char smem_raw[];
    uint4* sres0 = (uint4*)smem_raw;                       // 98304 B (Whh0 / dWhh)
    uint4* sres1 = (uint4*)(smem_raw + 98304);             // 98304 B (Whh1)
    uint4* ring  = (uint4*)(smem_raw + 196608);            // 12288 B (Wih1 stream)
    float* sh_x  = (float*)(smem_raw + 208896);            // 12288 B [b][24]
    float* sh_wi = (float*)(smem_raw + 221184);            // 4608 B
    const uint ring_addr = (uint)__cvta_generic_to_shared(ring);

    const int t = threadIdx.x;
    const int w = t >> 5;
    const int lane = t & 31;
    const int bid = blockIdx.x;
    const int kb = bid & 1;
    const int u0g = (bid >> 1) * 16;
    const int teach = teacher[0];
    const bool owner = ((w >> 2) == kb);

    // ---- zero h1 buffer 0 ----
    {
        int gid = bid * NTHR + t;             // 32768 == uint4 count of g_A1[0]
        ((uint4*)g_A1)[gid] = make_uint4(0, 0, 0, 0);
    }

    // ---- split + permute weights (own slice) ----
    {
        const float* Wm[4] = {eWhh0, eWih1, eWhh1, dWhh};
        for (int i = t; i < 4 * 6144; i += NTHR) {
            int m = i / 6144, r = i % 6144;
            int hc = r / 384, r2 = r % 384;
            int nf = r2 / 64, pl = (r2 >> 5) & 1, ln = r2 & 31;
            int g = nf >> 1, uu = (nf & 1) * 8 + (ln >> 2);
            long wrow = (long)(g * HH + u0g + uu) * HH;
            int kbase = kb * 512 + hc * 32;
            uint vals[4];
            #pragma unroll
            for (int c = 0; c < 4; c++) {
                int k0 = kbase + (c >> 1) * 16 + (c & 1) * 8 + (ln & 3) * 2;
                float2 xv = *reinterpret_cast<const float2*>(Wm[m] + wrow + k0);
                __nv_bfloat16 h0 = __float2bfloat16(xv.x);
                __nv_bfloat16 h1 = __float2bfloat16(xv.y);
                if (pl) {
                    h0 = __float2bfloat16(xv.x - __bfloat162float(h0));
                    h1 = __float2bfloat16(xv.y - __bfloat162float(h1));
                }
                vals[c] = (uint)__bfloat16_as_ushort(h0) |
                          ((uint)__bfloat16_as_ushort(h1) << 16);
            }
            g_B[m][bid][r] = make_uint4(vals[0], vals[1], vals[2], vals[3]);
        }
    }
    __syncthreads();
    // ---- resident copies + small tables ----
    for (int r = t; r < 6144; r += NTHR) {
        sres0[r] = g_B[0][bid][r];
        sres1[r] = g_B[2][bid][r];
    }
    load_wi48(eWih0, u0g, sh_wi);
    for (int idx = t; idx < BB * 24; idx += NTHR) {
        int b = idx / 24, k = idx % 24;
        sh_x[idx] = (k < FF) ? feats[((long)b * FROWS) * FF + k]
                             : labels[((long)b * TT) * LL + (k - FF)];
    }
    __syncthreads();

    // ---- prologue: h0(0) = GRU(x(0), h=0) ----
    if (owner) {
        float xp[6][4], zg[6][4];
        #pragma unroll
        for (int nf = 0; nf < 6; nf++)
            #pragma unroll
            for (int i = 0; i < 4; i++) zg[nf][i] = 0.f;
        xproj48(sh_x, sh_wi, w, lane, xp);
        upd48(xp, zg, ebih0, ebhh0, u0g, w, lane,
              nullptr, nullptr, g_A0[0][0], g_A0[0][1]);
    }
    gbar();

    float accS[6][4], accR[6][4], accC[6][4];
    const uint4* gWih1 = g_B[1][bid];

    // ================= encoder ==============================================
    for (int step = 0; step < TT; step++) {
        int rb = step & 1, wb = rb ^ 1;

        if (step + 1 < TT) {
            for (int idx = t; idx < BB * 24; idx += NTHR) {
                int b = idx / 24, k = idx % 24;
                sh_x[idx] = (k < FF) ? feats[((long)b * FROWS + step + 1) * FF + k]
                                     : labels[((long)b * TT + step + 1) * LL + (k - FF)];
            }
        }

        // dual: A = h0(step), S = Wih1 (gi1), R = Whh0 (gh0 for t+1)
        gemm_dual(g_A0[rb][0], g_A0[rb][1], sres0, ring, ring_addr, gWih1,
                  w, kb, lane, t, accS, accR);
        // single: A = h1(step-1), Whh1 (gh1)
        gemm_res(g_A1[rb][0], g_A1[rb][1], sres1, w, kb, lane, accC);

        float xp[6][4];
        if (owner) {
            if (step + 1 < TT) xproj48(sh_x, sh_wi, w, lane, xp);
        } else {
            part_write(bid, w, lane, accS, 0);
            part_write(bid, w, lane, accR, 1);
            part_write(bid, w, lane, accC, 2);
        }
        __threadfence();
        CLUSTER_SYNC();

        if (owner) {
            part_add(bid, w, lane, accS, 0);
            part_add(bid, w, lane, accR, 1);
            part_add(bid, w, lane, accC, 2);
            // h1(step) = GRU(gi=accS, gh=accC)
            upd48(accS, accC, ebih1, ebhh1, u0g, w, lane,
                  g_A1[rb][0], g_A1[rb][1], g_A1[wb][0], g_A1[wb][1]);
            // h0(step+1) = GRU(xp, gh=accR)
            if (step + 1 < TT)
                upd48(xp, accR, ebih0, ebhh0, u0g, w, lane,
                      g_A0[rb][0], g_A0[rb][1], g_A0[wb][0], g_A0[wb][1]);
        }
        gbar();
    }

    // ps -> out[0] + seed g_p (final h1 in buffer 0)
    fc_phase(g_A1[0][0], g_A1[0][1], fcW, fcb, out);
    load_wi48(dWih, u0g, sh_wi);
    for (int r = t; r < 6144; r += NTHR) sres0[r] = g_B[3][bid][r];   // dWhh
    gbar();

    // ================= decoder ==============================================
    for (int s = 0; s < PREDN - 1; s++) {
        int rb = s & 1, wb = rb ^ 1;
        for (int idx = t; idx < BB * 24; idx += NTHR) {
            int b = idx / 24, k = idx % 24;
            float v;
            if (k < FF)      v = feats[((long)b * FROWS + TT + s) * FF + k];
            else if (teach)  v = y[((long)b * (PREDN - 1) + s) * LL + (k - FF)];
            else             v = __ldcg(g_p + b * LL + (k - FF));
            sh_x[idx] = v;
        }
        __syncthreads();

        gemm_res(g_A1[rb][0], g_A1[rb][1], sres0, w, kb, lane, accC);

        float xp[6][4];
        if (owner) xproj48(sh_x, sh_wi, w, lane, xp);
        else       part_write(bid, w, lane, accC, 0);
        __threadfence();
        CLUSTER_SYNC();

        if (owner) {
            part_add(bid, w, lane, accC, 0);
            upd48(xp, accC, dbih, dbhh, u0g, w, lane,
                  g_A1[rb][0], g_A1[rb][1], g_A1[wb][0], g_A1[wb][1]);
        }
        gbar();

        fc_phase(g_A1[wb][0], g_A1[wb][1], fcW, fcb, out + (long)(s + 1) * BB * LL);
        gbar();
    }
}

extern "C" void kernel_launch(void* const* d_in, const int* in_sizes, int n_in,
                              void* d_out, int out_size) {
    const float* feats  = (const float*)d_in[0];
    const float* labels = (const float*)d_in[1];
    const float* y      = (const float*)d_in[2];
    const int*   teach  = (const int*)d_in[3];
    const float* eWih0  = (const float*)d_in[4];
    const float* eWhh0  = (const float*)d_in[5];
    const float* ebih0  = (const float*)d_in[6];
    const float* ebhh0  = (const float*)d_in[7];
    const float* eWih1  = (const float*)d_in[8];
    const float* eWhh1  = (const float*)d_in[9];
    const float* ebih1  = (const float*)d_in[10];
    const float* ebhh1  = (const float*)d_in[11];
    const float* dWih   = (const float*)d_in[12];
    const float* dWhh   = (const float*)d_in[13];
    const float* dbih   = (const float*)d_in[14];
    const float* dbhh   = (const float*)d_in[15];
    const float* fcW    = (const float*)d_in[16];
    const float* fcb    = (const float*)d_in[17];
    float* out = (float*)d_out;

    static int smem_set = 0;
    if (!smem_set) {
        cudaFuncSetAttribute(gru_persistent,
                             cudaFuncAttributeMaxDynamicSharedMemorySize, 225792);
        smem_set = 1;
    }

    gru_persistent<<<NBLK, NTHR, 225792>>>(feats, labels, y, teach,
                                           eWih0, eWhh0, ebih0, ebhh0,
                                           eWih1, eWhh1, ebih1, ebhh1,
                                           dWih, dWhh, dbih, dbhh,
                                           fcW, fcb, out);
}

// round 11
// speedup vs baseline: 1.4346x; 1.4346x over previous
#include <cuda_runtime.h>
#include <cuda_bf16.h>

#define NBLK 128
#define NTHR 384
#define BB   128
#define TT   512
#define PREDN 24
#define FF   16
#define LL   8
#define HH   1024
#define FROWS (TT + PREDN - 1)

typedef unsigned int uint;

#define BARG1() asm volatile("bar.sync 1, 256;" ::: "memory")
#define BARG2() asm volatile("bar.sync 2, 128;" ::: "memory")

// ---------------- persistent device scratch ---------------------------------
__device__ uint4 g_A0[2][2][8 * 64 * 32];   // hidden states, MMA A-frag order
__device__ uint4 g_A1[2][2][8 * 64 * 32];
__device__ uint4 g_B[4][NBLK][3][32][2][32]; // [mat][bid][nf][hc][pl][ln]
__device__ float g_p[BB * LL];
__device__ unsigned g_count = 0;
__device__ unsigned g_gen = 0;

// ---------------- grid barrier ----------------------------------------------
__device__ __forceinline__ void gbar() {
    __syncthreads();
    if (threadIdx.x == 0) {
        __threadfence();
        volatile unsigned* vg = &g_gen;
        unsigned g = *vg;
        if (atomicAdd(&g_count, 1u) == NBLK - 1) {
            g_count = 0;
            __threadfence();
            *vg = g + 1;
        } else {
            while (*vg == g) {}
        }
        __threadfence();
    }
    __syncthreads();
}

// ---------------- 2B coherent global ld/st ----------------------------------
__device__ __forceinline__ unsigned short ldcg_u16(const void* p) {
    unsigned short v;
    asm volatile("ld.global.cg.u16 %0, [%1];" : "=h"(v) : "l"(p));
    return v;
}
__device__ __forceinline__ void stcg_u16(void* p, unsigned short v) {
    asm volatile("st.global.cg.u16 [%0], %1;" :: "l"(p), "h"(v));
}

// ---------------- h element <-> fragment-layout mapping ----------------------
__device__ __forceinline__ int h_off(int b, int u) {
    int rg = b >> 4, r = b & 15, kp = u & 15, kg = u >> 4;
    int ireg = (r >> 3) + ((kp >> 3) << 1);
    int ln = (r & 7) * 4 + ((kp & 7) >> 1);
    return ((rg * 64 + kg) * 32 + ln) * 16 + ireg * 4 + (kp & 1) * 2;
}
__device__ __forceinline__ void store_h(uint4* Ph, uint4* Pl, int b, int u, float v) {
    __nv_bfloat16 hi = __float2bfloat16(v);
    __nv_bfloat16 lo = __float2bfloat16(v - __bfloat162float(hi));
    int off = h_off(b, u);
    stcg_u16((char*)Ph + off, __bfloat16_as_ushort(hi));
    stcg_u16((char*)Pl + off, __bfloat16_as_ushort(lo));
}
__device__ __forceinline__ float load_h(const uint4* Ph, const uint4* Pl, int b, int u) {
    int off = h_off(b, u);
    float hi = __bfloat162float(__ushort_as_bfloat16(ldcg_u16((const char*)Ph + off)));
    float lo = __bfloat162float(__ushort_as_bfloat16(ldcg_u16((const char*)Pl + off)));
    return hi + lo;
}

// ---------------- HMMA m16n8k16 bf16 -> f32 ----------------------------------
__device__ __forceinline__ void mma16816(float* c, const uint* a, uint b0, uint b1) {
    asm volatile(
        "mma.sync.aligned.m16n8k16.row.col.f32.bf16.bf16.f32 "
        "{%0,%1,%2,%3}, {%4,%5,%6,%7}, {%8,%9}, {%0,%1,%2,%3};"
        : "+f"(c[0]), "+f"(c[1]), "+f"(c[2]), "+f"(c[3])
        : "r"(a[0]), "r"(a[1]), "r"(a[2]), "r"(a[3]), "r"(b0), "r"(b1));
}

// ---------------- cp.async staging --------------------------------------------
// group0 ring slot: 1536 uint4, layout ((set*4+hcg)*6 + nf*2+pl)*32 + ln
__device__ __forceinline__ void issue0(const uint4* __restrict__ B0,
                                       const uint4* __restrict__ B1,
                                       const int* offs, int hc0, uint dst, int t) {
    const uint4* base = ((t < 128) ? B0 : B1) + hc0 * 64;
    uint d = dst + t * 96;
    #pragma unroll
    for (int j = 0; j < 6; j++)
        asm volatile("cp.async.cg.shared.global [%0], [%1], 16;"
                     :: "r"(d + j * 16), "l"(base + offs[j]) : "memory");
}
// group1 ring slot: 768 uint4, layout (hcg*6 + nf*2+pl)*32 + ln
__device__ __forceinline__ void issue1(const uint4* __restrict__ B,
                                       const int* offs, int hc0, uint dst, int s1) {
    const uint4* base = B + hc0 * 64;
    uint d = dst + s1 * 96;
    #pragma unroll
    for (int j = 0; j < 6; j++)
        asm volatile("cp.async.cg.shared.global [%0], [%1], 16;"
                     :: "r"(d + j * 16), "l"(base + offs[j]) : "memory");
}

// ---------------- group0: dual GEMM (8 warps, threads 0-255) ------------------
// Warp w rows [16w,16w+16), all 24 cols, K=1024. accS <- B0 (set0), accR <- B1.
__device__ void gemm_dual(const uint4* __restrict__ Ah, const uint4* __restrict__ Al,
                          const uint4* __restrict__ B0, const uint4* __restrict__ B1,
                          const int* offs, uint4* __restrict__ sB, uint sb_addr,
                          int w, int lane, int t,
                          float accS[3][4], float accR[3][4]) {
    #pragma unroll
    for (int nf = 0; nf < 3; nf++)
        #pragma unroll
        for (int i = 0; i < 4; i++) { accS[nf][i] = 0.f; accR[nf][i] = 0.f; }

    const uint4* Abh = Ah + w * 2048 + lane;
    const uint4* Abl = Al + w * 2048 + lane;

    BARG1();
    issue0(B0, B1, offs, 0, sb_addr, t);
    asm volatile("cp.async.commit_group;" ::: "memory");
    issue0(B0, B1, offs, 4, sb_addr + 24576, t);
    asm volatile("cp.async.commit_group;" ::: "memory");

    uint4 fah[4][2], fal[4][2];
    #pragma unroll
    for (int j = 0; j < 4; j++) {
        fah[j][0] = __ldcg(Abh + j * 64);   fah[j][1] = __ldcg(Abh + j * 64 + 32);
        fal[j][0] = __ldcg(Abl + j * 64);   fal[j][1] = __ldcg(Abl + j * 64 + 32);
    }

    #pragma unroll 1
    for (int g = 0; g < 8; g++) {
        asm volatile("cp.async.wait_group 1;" ::: "memory");
        BARG1();
        if (g + 2 < 8) issue0(B0, B1, offs, (g + 2) * 4, sb_addr + ((g + 2) % 3) * 24576, t);
        asm volatile("cp.async.commit_group;" ::: "memory");
        const uint4* sbuf = sB + (g % 3) * 1536;
        #pragma unroll
        for (int j = 0; j < 4; j++) {
            #pragma unroll
            for (int s = 0; s < 2; s++) {
                float (*acc)[4] = s ? accR : accS;
                #pragma unroll
                for (int nf = 0; nf < 3; nf++) {
                    uint4 BH = sbuf[((s * 4 + j) * 6 + nf * 2) * 32 + lane];
                    uint4 BL = sbuf[((s * 4 + j) * 6 + nf * 2 + 1) * 32 + lane];
                    const uint* a0h = (const uint*)&fah[j][0];
                    const uint* a0l = (const uint*)&fal[j][0];
                    const uint* a1h = (const uint*)&fah[j][1];
                    const uint* a1l = (const uint*)&fal[j][1];
                    mma16816(acc[nf], a0h, BH.x, BH.y);
                    mma16816(acc[nf], a0l, BH.x, BH.y);
                    mma16816(acc[nf], a0h, BL.x, BL.y);
                    mma16816(acc[nf], a1h, BH.z, BH.w);
                    mma16816(acc[nf], a1l, BH.z, BH.w);
                    mma16816(acc[nf], a1h, BL.z, BL.w);
                }
            }
            int nhc = 4 * g + 4 + j;
            if (nhc < 32) {
                fah[j][0] = __ldcg(Abh + nhc * 64);  fah[j][1] = __ldcg(Abh + nhc * 64 + 32);
                fal[j][0] = __ldcg(Abl + nhc * 64);  fal[j][1] = __ldcg(Abl + nhc * 64 + 32);
            }
        }
    }
}

// ---------------- group1: single GEMM (4 warps, threads 256-383) --------------
// Warp w1 owns 2 m-tiles (rows [32w1,32w1+32)), all 24 cols, K=1024.
__device__ void gemm1(const uint4* __restrict__ Ah, const uint4* __restrict__ Al,
                      const uint4* __restrict__ Bsrc, const int* offs,
                      uint4* __restrict__ sR, uint sr_addr,
                      int w1, int lane, int s1, float acc[2][3][4]) {
    #pragma unroll
    for (int mt = 0; mt < 2; mt++)
        #pragma unroll
        for (int nf = 0; nf < 3; nf++)
            #pragma unroll
            for (int i = 0; i < 4; i++) acc[mt][nf][i] = 0.f;

    const uint4* Abh0 = Ah + (2 * w1) * 2048 + lane;
    const uint4* Abl0 = Al + (2 * w1) * 2048 + lane;
    const uint4* Abh1 = Abh0 + 2048;
    const uint4* Abl1 = Abl0 + 2048;

    BARG2();
    issue1(Bsrc, offs, 0, sr_addr, s1);
    asm volatile("cp.async.commit_group;" ::: "memory");
    issue1(Bsrc, offs, 4, sr_addr + 12288, s1);
    asm volatile("cp.async.commit_group;" ::: "memory");

    uint4 fah[2][2][2], fal[2][2][2];   // [buf][tile][kgl]
    #pragma unroll
    for (int d = 0; d < 2; d++) {
        fah[d][0][0] = __ldcg(Abh0 + d * 64);  fah[d][0][1] = __ldcg(Abh0 + d * 64 + 32);
        fal[d][0][0] = __ldcg(Abl0 + d * 64);  fal[d][0][1] = __ldcg(Abl0 + d * 64 + 32);
        fah[d][1][0] = __ldcg(Abh1 + d * 64);  fah[d][1][1] = __ldcg(Abh1 + d * 64 + 32);
        fal[d][1][0] = __ldcg(Abl1 + d * 64);  fal[d][1][1] = __ldcg(Abl1 + d * 64 + 32);
    }

    #pragma unroll 1
    for (int g = 0; g < 8; g++) {
        asm volatile("cp.async.wait_group 1;" ::: "memory");
        BARG2();
        if (g + 2 < 8) issue1(Bsrc, offs, (g + 2) * 4, sr_addr + ((g + 2) % 3) * 12288, s1);
        asm volatile("cp.async.commit_group;" ::: "memory");
        const uint4* sbuf = sR + (g % 3) * 768;
        #pragma unroll
        for (int j = 0; j < 4; j++) {
            int hc = 4 * g + j;
            int d = hc & 1;
            uint4 BH[3], BL[3];
            #pragma unroll
            for (int nf = 0; nf < 3; nf++) {
                BH[nf] = sbuf[(j * 6 + nf * 2) * 32 + lane];
                BL[nf] = sbuf[(j * 6 + nf * 2 + 1) * 32 + lane];
            }
            #pragma unroll
            for (int mt = 0; mt < 2; mt++) {
                const uint* a0h = (const uint*)&fah[d][mt][0];
                const uint* a0l = (const uint*)&fal[d][mt][0];
                const uint* a1h = (const uint*)&fah[d][mt][1];
                const uint* a1l = (const uint*)&fal[d][mt][1];
                #pragma unroll
                for (int nf = 0; nf < 3; nf++) {
                    mma16816(acc[mt][nf], a0h, BH[nf].x, BH[nf].y);
                    mma16816(acc[mt][nf], a0l, BH[nf].x, BH[nf].y);
                    mma16816(acc[mt][nf], a0h, BL[nf].x, BL[nf].y);
                    mma16816(acc[mt][nf], a1h, BH[nf].z, BH[nf].w);
                    mma16816(acc[mt][nf], a1l, BH[nf].z, BH[nf].w);
                    mma16816(acc[mt][nf], a1h, BL[nf].z, BL[nf].w);
                }
            }
            int nhc = hc + 2;
            if (nhc < 32) {
                fah[d][0][0] = __ldcg(Abh0 + nhc * 64);  fah[d][0][1] = __ldcg(Abh0 + nhc * 64 + 32);
                fal[d][0][0] = __ldcg(Abl0 + nhc * 64);  fal[d][0][1] = __ldcg(Abl0 + nhc * 64 + 32);
                fah[d][1][0] = __ldcg(Abh1 + nhc * 64);  fah[d][1][1] = __ldcg(Abh1 + nhc * 64 + 32);
                fal[d][1][0] = __ldcg(Abl1 + nhc * 64);  fal[d][1][1] = __ldcg(Abl1 + nhc * 64 + 32);
            }
        }
    }
}

// ---------------- in-register GRU update (group0, per MMA lane) ----------------
__device__ __forceinline__ float sigf(float x) { return 1.f / (1.f + __expf(-x)); }

__device__ __forceinline__ void upd_lane(const float gi[3][4], const float gh[3][4],
                                         const float* __restrict__ bih,
                                         const float* __restrict__ bhh,
                                         int u0, int w, int lane,
                                         const uint4* Phc, const uint4* Plc,
                                         uint4* Phn, uint4* Pln) {
    int r0 = w * 16 + (lane >> 2);
    int c2 = (lane & 3) * 2;
    float bi[2][3], bh[2][3];
    #pragma unroll
    for (int q = 0; q < 2; q++) {
        int jc = u0 + c2 + q;
        bi[q][0] = __ldg(bih + jc);
        bi[q][1] = __ldg(bih + HH + jc);
        bi[q][2] = __ldg(bih + 2 * HH + jc);
        bh[q][0] = __ldg(bhh + jc);
        bh[q][1] = __ldg(bhh + HH + jc);
        bh[q][2] = __ldg(bhh + 2 * HH + jc);
    }
    #pragma unroll
    for (int i = 0; i < 4; i++) {
        int b = r0 + (i >> 1) * 8;
        int q = i & 1;
        int jc = u0 + c2 + q;
        float r = sigf(gi[0][i] + bi[q][0] + gh[0][i] + bh[q][0]);
        float z = sigf(gi[1][i] + bi[q][1] + gh[1][i] + bh[q][1]);
        float n = tanhf(gi[2][i] + bi[q][2] + r * (gh[2][i] + bh[q][2]));
        float ho = Phc ? load_h(Phc, Plc, b, jc) : 0.f;
        store_h(Phn, Pln, b, jc, (1.f - z) * n + z * ho);
    }
}

__device__ __forceinline__ void xproj_lane(const float* __restrict__ sh_x,
                                           const float* __restrict__ sh_wi,
                                           int w, int lane, float ai[3][4]) {
    int r0 = w * 16 + (lane >> 2);
    int c2 = (lane & 3) * 2;
    #pragma unroll
    for (int i = 0; i < 4; i++) {
        int b = r0 + (i >> 1) * 8;
        int u = c2 + (i & 1);
        float a0 = 0.f, a1 = 0.f, a2 = 0.f;
        #pragma unroll
        for (int k = 0; k < 24; k++) {
            float xv = sh_x[b * 25 + k];
            a0 += xv * sh_wi[k * 24 + u];
            a1 += xv * sh_wi[k * 24 + 8 + u];
            a2 += xv * sh_wi[k * 24 + 16 + u];
        }
        ai[0][i] = a0; ai[1][i] = a1; ai[2][i] = a2;
    }
}

// ---------------- misc helpers ------------------------------------------------
__device__ __forceinline__ void load_wi_slice(const float* __restrict__ Wih, int u0,
                                              float* __restrict__ sh_wi) {
    for (int idx = threadIdx.x; idx < 24 * 24; idx += NTHR) {
        int jl = idx / 24, k = idx % 24;
        int g = jl >> 3, uu = jl & 7;
        sh_wi[k * 24 + jl] = Wih[(long)(g * HH + u0 + uu) * 24 + k];
    }
}

__device__ __forceinline__ void fc_phase(const uint4* Ph, const uint4* Pl,
                                         const float* __restrict__ fcW,
                                         const float* __restrict__ fcb,
                                         float* __restrict__ outp) {
    int b = blockIdx.x;
    int w = threadIdx.x >> 5;
    int lane = threadIdx.x & 31;
    float s = 0.f;
    #pragma unroll
    for (int c = 0; c < 32; c++) {
        int u = c * 32 + lane;
        s += load_h(Ph, Pl, b, u) * fcW[(long)w * HH + u];
    }
    #pragma unroll
    for (int o = 16; o; o >>= 1) s += __shfl_down_sync(0xffffffffu, s, o);
    if (lane == 0) {
        float v = s + fcb[w];
        outp[b * LL + w] = v;
        asm volatile("st.global.cg.f32 [%0], %1;" :: "l"(g_p + b * LL + w), "f"(v));
    }
}

// ---------------- persistent kernel -----------------------------------------
__global__ void __launch_bounds__(NTHR, 1) gru_persistent(
    const float* __restrict__ feats, const float* __restrict__ labels,
    const float* __restrict__ y, const int* __restrict__ teacher,
    const float* __restrict__ eWih0, const float* __restrict__ eWhh0,
    const float* __restrict__ ebih0, const float* __restrict__ ebhh0,
    const float* __restrict__ eWih1, const float* __restrict__ eWhh1,
    const float* __restrict__ ebih1, const float* __restrict__ ebhh1,
    const float* __restrict__ dWih, const float* __restrict__ dWhh,
    const float* __restrict__ dbih, const float* __restrict__ dbhh,
    const float* __restrict__ fcW, const float* __restrict__ fcb,
    float* __restrict__ out)
{
    extern __shared__ __align__(16) unsigned char smem_raw[];
    uint4* sB0   = (uint4*)smem_raw;                        // 73728 B (group0 ring)
    uint4* sR1   = (uint4*)(smem_raw + 73728);              // 36864 B (group1 ring)
    float* gates = (float*)(smem_raw + 110592);             // 12288 B (gh1 exchange)
    float* sh_x  = (float*)(smem_raw + 122880);             // 12800 B
    float* sh_wi = (float*)(smem_raw + 135680);             // 2304 B
    const uint sb0_addr = (uint)__cvta_generic_to_shared(sB0);
    const uint sr1_addr = (uint)__cvta_generic_to_shared(sR1);

    const int t = threadIdx.x;
    const int lane = t & 31;
    const int u0 = blockIdx.x * 8;
    const int teach = teacher[0];
    const bool isg0 = (t < 256);
    const int w = t >> 5;            // group0 warp id (0-7 when isg0)
    const int w1 = (t - 256) >> 5;   // group1 warp id (0-3)
    const int s1 = t - 256;          // group1 staging index

    // per-thread cp.async source offsets (shared formula, s in [0,256))
    int offs[6];
    {
        int s = isg0 ? t : s1;
        #pragma unroll
        for (int j = 0; j < 6; j++) {
            int li = s * 6 + j;
            int ln = li & 31;
            int q = li >> 5;
            int sub = q % 6;
            int hcg = (q / 6) & 3;
            int nf = sub >> 1, pl = sub & 1;
            offs[j] = nf * 2048 + hcg * 64 + pl * 32 + ln;
        }
    }

    const uint4* Bb0 = &g_B[0][blockIdx.x][0][0][0][0];   // eWhh0
    const uint4* Bb1 = &g_B[1][blockIdx.x][0][0][0][0];   // eWih1
    const uint4* Bb2 = &g_B[2][blockIdx.x][0][0][0][0];   // eWhh1
    const uint4* Bb3 = &g_B[3][blockIdx.x][0][0][0][0];   // dWhh

    // ---- zero h1 buffer 0 (h1(-1) = 0), both planes ----
    {
        int gid = blockIdx.x * NTHR + t;
        if (gid < 32768) ((uint4*)g_A1)[gid] = make_uint4(0, 0, 0, 0);
    }

    // ---- split + permute weights into fragment order (per-block slice) ----
    {
        const float* Wm[4] = {eWhh0, eWih1, eWhh1, dWhh};
        for (int wdx = t; wdx < 4 * 3 * 32 * 2 * 32; wdx += NTHR) {
            int ln = wdx & 31;
            int pl = (wdx >> 5) & 1;
            int hc = (wdx >> 6) & 31;
            int rest = wdx >> 11;
            int nw = rest % 3, m = rest / 3;
            const float* W = Wm[m];
            int u = ln >> 2;
            long wr = (long)(nw * HH + u0 + u) * HH;
            uint vals[4];
            #pragma unroll
            for (int c = 0; c < 4; c++) {
                int k0 = hc * 32 + (c >> 1) * 16 + (c & 1) * 8 + (ln & 3) * 2;
                float2 xv = *reinterpret_cast<const float2*>(W + wr + k0);
                __nv_bfloat16 h0 = __float2bfloat16(xv.x);
                __nv_bfloat16 h1 = __float2bfloat16(xv.y);
                if (pl) {
                    h0 = __float2bfloat16(xv.x - __bfloat162float(h0));
                    h1 = __float2bfloat16(xv.y - __bfloat162float(h1));
                }
                vals[c] = (uint)__bfloat16_as_ushort(h0) |
                          ((uint)__bfloat16_as_ushort(h1) << 16);
            }
            g_B[m][blockIdx.x][nw][hc][pl][ln] = make_uint4(vals[0], vals[1], vals[2], vals[3]);
        }
    }
    load_wi_slice(eWih0, u0, sh_wi);

    // ---- prologue: h0(0) = GRU(x(0), h=0) -> g_A0[0] ----
    for (int idx = t; idx < BB * 24; idx += NTHR) {
        int b = idx / 24, k = idx % 24;
        sh_x[b * 25 + k] = (k < FF) ? feats[((long)b * FROWS) * FF + k]
                                    : labels[((long)b * TT) * LL + (k - FF)];
    }
    __syncthreads();
    if (isg0) {
        float ai[3][4], zg[3][4];
        #pragma unroll
        for (int g = 0; g < 3; g++)
            #pragma unroll
            for (int i = 0; i < 4; i++) zg[g][i] = 0.f;
        xproj_lane(sh_x, sh_wi, w, lane, ai);
        upd_lane(ai, zg, ebih0, ebhh0, u0, w, lane,
                 nullptr, nullptr, g_A0[0][0], g_A0[0][1]);
    }
    gbar();

    // ================= encoder: warp-specialized, 1 gbar/step ================
    for (int step = 0; step < TT; step++) {
        int rb = step & 1, wb = rb ^ 1;

        if (step + 1 < TT) {
            for (int idx = t; idx < BB * 24; idx += NTHR) {
                int b = idx / 24, k = idx % 24;
                sh_x[b * 25 + k] = (k < FF) ? feats[((long)b * FROWS + step + 1) * FF + k]
                                            : labels[((long)b * TT + step + 1) * LL + (k - FF)];
            }
        }

        float accS[3][4], accR[3][4];
        if (isg0) {
            // A = h0(step): accS = Wih1 gates (gi1), accR = Whh0 gates (t+1)
            gemm_dual(g_A0[rb][0], g_A0[rb][1], Bb1, Bb0, offs, sB0, sb0_addr,
                      w, lane, t, accS, accR);
        } else {
            // A = h1(step-1): gh1 = Whh1 gates (2 m-tiles/warp)
            float acc[2][3][4];
            gemm1(g_A1[rb][0], g_A1[rb][1], Bb2, offs, sR1, sr1_addr,
                  w1, lane, s1, acc);
            #pragma unroll
            for (int mt = 0; mt < 2; mt++) {
                float* gp = gates + ((2 * w1 + mt) * 32 + lane) * 12;
                #pragma unroll
                for (int nf = 0; nf < 3; nf++)
                    #pragma unroll
                    for (int i = 0; i < 4; i++) gp[nf * 4 + i] = acc[mt][nf][i];
            }
        }
        __syncthreads();

        if (isg0) {
            float ghl[3][4];
            const float* gp = gates + (w * 32 + lane) * 12;
            #pragma unroll
            for (int nf = 0; nf < 3; nf++)
                #pragma unroll
                for (int i = 0; i < 4; i++) ghl[nf][i] = gp[nf * 4 + i];
            // h1(step) = GRU(gi=accS, gh=ghl, h1_old)
            upd_lane(accS, ghl, ebih1, ebhh1, u0, w, lane,
                     g_A1[rb][0], g_A1[rb][1], g_A1[wb][0], g_A1[wb][1]);
            // h0(step+1) = GRU(xproj(step+1), gh=accR, h0_old)
            if (step + 1 < TT) {
                float ai[3][4];
                xproj_lane(sh_x, sh_wi, w, lane, ai);
                upd_lane(ai, accR, ebih0, ebhh0, u0, w, lane,
                         g_A0[rb][0], g_A0[rb][1], g_A0[wb][0], g_A0[wb][1]);
            }
        }
        gbar();
    }

    // ps -> out[0] + seed g_p (final h1 in buffer 0)
    if (isg0) fc_phase(g_A1[0][0], g_A1[0][1], fcW, fcb, out);
    load_wi_slice(dWih, u0, sh_wi);
    gbar();

    // ================= decoder ==============================================
    for (int s = 0; s < PREDN - 1; s++) {
        int rb = s & 1, wb = rb ^ 1;
        for (int idx = t; idx < BB * 24; idx += NTHR) {
            int b = idx / 24, k = idx % 24;
            float v;
            if (k < FF)      v = feats[((long)b * FROWS + TT + s) * FF + k];
            else if (teach)  v = y[((long)b * (PREDN - 1) + s) * LL + (k - FF)];
            else             v = __ldcg(g_p + b * LL + (k - FF));
            sh_x[b * 25 + k] = v;
        }

        if (!isg0) {
            float acc[2][3][4];
            gemm1(g_A1[rb][0], g_A1[rb][1], Bb3, offs, sR1, sr1_addr,
                  w1, lane, s1, acc);
            #pragma unroll
            for (int mt = 0; mt < 2; mt++) {
                float* gp = gates + ((2 * w1 + mt) * 32 + lane) * 12;
                #pragma unroll
                for (int nf = 0; nf < 3; nf++)
                    #pragma unroll
                    for (int i = 0; i < 4; i++) gp[nf * 4 + i] = acc[mt][nf][i];
            }
        }
        __syncthreads();

        if (isg0) {
            float ai[3][4], ghl[3][4];
            xproj_lane(sh_x, sh_wi, w, lane, ai);
            const float* gp = gates + (w * 32 + lane) * 12;
            #pragma unroll
            for (int nf = 0; nf < 3; nf++)
                #pragma unroll
                for (int i = 0; i < 4; i++) ghl[nf][i] = gp[nf * 4 + i];
            upd_lane(ai, ghl, dbih, dbhh, u0, w, lane,
                     g_A1[rb][0], g_A1[rb][1], g_A1[wb][0], g_A1[wb][1]);
        }
        gbar();

        if (isg0) fc_phase(g_A1[wb][0], g_A1[wb][1], fcW, fcb,
                           out + (long)(s + 1) * BB * LL);
        gbar();
    }
}

extern "C" void kernel_launch(void* const* d_in, const int* in_sizes, int n_in,
                              void* d_out, int out_size) {
    const float* feats  = (const float*)d_in[0];
    const float* labels = (const float*)d_in[1];
    const float* y      = (const float*)d_in[2];
    const int*   teach  = (const int*)d_in[3];
    const float* eWih0  = (const float*)d_in[4];
    const float* eWhh0  = (const float*)d_in[5];
    const float* ebih0  = (const float*)d_in[6];
    const float* ebhh0  = (const float*)d_in[7];
    const float* eWih1  = (const float*)d_in[8];
    const float* eWhh1  = (const float*)d_in[9];
    const float* ebih1  = (const float*)d_in[10];
    const float* ebhh1  = (const float*)d_in[11];
    const float* dWih   = (const float*)d_in[12];
    const float* dWhh   = (const float*)d_in[13];
    const float* dbih   = (const float*)d_in[14];
    const float* dbhh   = (const float*)d_in[15];
    const float* fcW    = (const float*)d_in[16];
    const float* fcb    = (const float*)d_in[17];
    float* out = (float*)d_out;

    static int smem_set = 0;
    if (!smem_set) {
        cudaFuncSetAttribute(gru_persistent,
                             cudaFuncAttributeMaxDynamicSharedMemorySize, 137984);
        smem_set = 1;
    }

    gru_persistent<<<NBLK, NTHR, 137984>>>(feats, labels, y, teach,
                                           eWih0, eWhh0, ebih0, ebhh0,
                                           eWih1, eWhh1, ebih1, ebhh1,
                                           dWih, dWhh, dbih, dbhh,
                                           fcW, fcb, out);
}